// round 1
// baseline (speedup 1.0000x reference)
#include <cuda_runtime.h>
#include <cstddef>

// Problem constants
constexpr int NB = 32;     // batch
constexpr int NS = 2048;   // sequence
constexpr int ND = 512;    // model dim
constexpr int NF = 512;    // dff
constexpr int C1 = 32;     // s-chunks for pass 1
constexpr int C2 = 32;     // s-chunks for pass 2
constexpr int NW = 8;      // warps per pass block (256 threads)
#define INV_SQRT_DFF 0.044194173824159216f  // 1/sqrt(512)

// Scratch (device globals; no allocation anywhere)
__device__ float g_xwp[C1 * NB * ND];  // partial xw per chunk
__device__ float g_xw[NB * ND];
__device__ float g_wsum;
__device__ float g_kw[NB * NF];
__device__ float g_u[NB * ND];
__device__ float g_c[NB];
__device__ float g_xtp[C2 * NB * ND];  // partial xt per chunk
__device__ float g_xt[NB * ND];
__device__ float g_Tp[C2 * NB];
__device__ float g_T[NB];

// ---------------------------------------------------------------------------
// Pass 1: xw[b,d] = sum_s Wt[s] * x[b,s,d]   (streams 128 MB of x)
// grid (NB, C1), 256 threads
// ---------------------------------------------------------------------------
__global__ __launch_bounds__(256) void k_xw(const float* __restrict__ x,
                                            const float* __restrict__ Wt) {
    const int b = blockIdx.x, c = blockIdx.y;
    const int tid = threadIdx.x, warp = tid >> 5, lane = tid & 31;
    const int rows = NS / C1;  // 64
    const int s0 = c * rows;

    __shared__ float s_wt[NS / C1];
    __shared__ float4 s4[NW * 128];

    if (tid < rows) s_wt[tid] = Wt[s0 + tid];
    __syncthreads();

    float4 acc[4] = {{0,0,0,0},{0,0,0,0},{0,0,0,0},{0,0,0,0}};
#pragma unroll 2
    for (int r = warp; r < rows; r += NW) {
        const float4* xp = (const float4*)x + ((size_t)b * NS + s0 + r) * (ND / 4);
        const float wt = s_wt[r];
#pragma unroll
        for (int j = 0; j < 4; j++) {
            float4 v = xp[32 * j + lane];
            acc[j].x += wt * v.x; acc[j].y += wt * v.y;
            acc[j].z += wt * v.z; acc[j].w += wt * v.w;
        }
    }
#pragma unroll
    for (int j = 0; j < 4; j++) s4[warp * 128 + 32 * j + lane] = acc[j];
    __syncthreads();

    // deterministic cross-warp reduce: thread tid handles d = tid and tid+256
    const float* s = (const float*)s4;
    float v0 = 0.f, v1 = 0.f;
#pragma unroll
    for (int w = 0; w < NW; w++) {
        v0 += s[w * 512 + tid];
        v1 += s[w * 512 + tid + 256];
    }
    float* dst = g_xwp + ((size_t)c * NB + b) * ND;
    dst[tid] = v0;
    dst[tid + 256] = v1;
}

// ---------------------------------------------------------------------------
// Reduce xw partials; block 0 also computes wsum = sum(Wt)
// grid 32, 512 threads
// ---------------------------------------------------------------------------
__global__ __launch_bounds__(512) void k_red1(const float* __restrict__ Wt) {
    const int i = blockIdx.x * 512 + threadIdx.x;
    float v = 0.f;
#pragma unroll
    for (int c = 0; c < C1; c++) v += g_xwp[(size_t)c * NB * ND + i];
    g_xw[i] = v;

    if (blockIdx.x == 0) {
        __shared__ float sr[512];
        float w = 0.f;
        for (int k = threadIdx.x; k < NS; k += 512) w += Wt[k];
        sr[threadIdx.x] = w;
        __syncthreads();
        for (int off = 256; off; off >>= 1) {
            if (threadIdx.x < off) sr[threadIdx.x] += sr[threadIdx.x + off];
            __syncthreads();
        }
        if (threadIdx.x == 0) g_wsum = sr[0];
    }
}

// ---------------------------------------------------------------------------
// kw[b,f] = Wk[f,:].xw[b,:] + bk[f]*wsum    (warp per output)
// grid (NB, NF/8), 256 threads
// ---------------------------------------------------------------------------
__global__ __launch_bounds__(256) void k_kw(const float* __restrict__ Wk,
                                            const float* __restrict__ bk) {
    const int b = blockIdx.x;
    const int warp = threadIdx.x >> 5, lane = threadIdx.x & 31;
    const int f = blockIdx.y * 8 + warp;

    const float4* wk = (const float4*)Wk + (size_t)f * (ND / 4);
    const float4* xw = (const float4*)(g_xw + b * ND);
    float dot = 0.f;
#pragma unroll
    for (int q = 0; q < 4; q++) {
        float4 wv = wk[32 * q + lane];
        float4 xv = xw[32 * q + lane];
        dot += wv.x * xv.x + wv.y * xv.y + wv.z * xv.z + wv.w * xv.w;
    }
#pragma unroll
    for (int off = 16; off; off >>= 1) dot += __shfl_xor_sync(0xffffffffu, dot, off);
    if (lane == 0) g_kw[b * NF + f] = dot + bk[f] * g_wsum;
}

// ---------------------------------------------------------------------------
// u[b,d] = sum_f Wq[f,d]*kw[b,f]  ;  c[b] = sum_f bq[f]*kw[b,f]
// grid (NB, 8), 512 threads. Each block: 64 d-columns, f split into 8 groups.
// ---------------------------------------------------------------------------
__global__ __launch_bounds__(512) void k_u(const float* __restrict__ Wq,
                                           const float* __restrict__ bq) {
    const int b = blockIdx.x;
    const int d0 = blockIdx.y * 64;
    const int tid = threadIdx.x;
    const int dl = tid & 63;        // 0..63 (coalesced within warp halves)
    const int fg = tid >> 6;        // 0..7

    __shared__ float s_kw[NF];
    __shared__ float s_red[512];

    s_kw[tid] = g_kw[b * NF + tid];
    __syncthreads();

    if (blockIdx.y == 0) {  // uniform per block
        s_red[tid] = bq[tid] * s_kw[tid];
        __syncthreads();
        for (int off = 256; off; off >>= 1) {
            if (tid < off) s_red[tid] += s_red[tid + off];
            __syncthreads();
        }
        if (tid == 0) g_c[b] = s_red[0];
    }
    __syncthreads();

    float acc = 0.f;
#pragma unroll 4
    for (int i = 0; i < 64; i++) {
        const int f = fg * 64 + i;
        acc += Wq[(size_t)f * ND + d0 + dl] * s_kw[f];
    }
    s_red[tid] = acc;
    __syncthreads();
    if (tid < 64) {
        float u = 0.f;
#pragma unroll
        for (int g = 0; g < 8; g++) u += s_red[g * 64 + tid];
        g_u[b * ND + d0 + tid] = u;
    }
}

// ---------------------------------------------------------------------------
// Pass 2: ta[b,s] = (x[b,s].u[b] + c[b])/sqrt(DFF) + bt
//         xt[b,d] += ta*x[b,s,d] ; T[b] += ta      (streams 128 MB of x)
// grid (NB, C2), 256 threads
// ---------------------------------------------------------------------------
__global__ __launch_bounds__(256) void k_pass2(const float* __restrict__ x,
                                               const float* __restrict__ bt) {
    const int b = blockIdx.x, c = blockIdx.y;
    const int tid = threadIdx.x, warp = tid >> 5, lane = tid & 31;
    const int rows = NS / C2;  // 64
    const int s0 = c * rows;

    __shared__ float4 s4[NW * 128];
    __shared__ float s_T[NW];

    const float4* up = (const float4*)(g_u + b * ND);
    float4 u4[4];
#pragma unroll
    for (int j = 0; j < 4; j++) u4[j] = up[32 * j + lane];
    const float cb = g_c[b];
    const float btv = bt[0];

    float4 acc[4] = {{0,0,0,0},{0,0,0,0},{0,0,0,0},{0,0,0,0}};
    float tsum = 0.f;

#pragma unroll 2
    for (int r = warp; r < rows; r += NW) {
        const float4* xp = (const float4*)x + ((size_t)b * NS + s0 + r) * (ND / 4);
        float4 xv[4];
#pragma unroll
        for (int j = 0; j < 4; j++) xv[j] = xp[32 * j + lane];
        float dot = 0.f;
#pragma unroll
        for (int j = 0; j < 4; j++)
            dot += xv[j].x * u4[j].x + xv[j].y * u4[j].y +
                   xv[j].z * u4[j].z + xv[j].w * u4[j].w;
#pragma unroll
        for (int off = 16; off; off >>= 1) dot += __shfl_xor_sync(0xffffffffu, dot, off);
        const float ta = (dot + cb) * INV_SQRT_DFF + btv;
        tsum += ta;
#pragma unroll
        for (int j = 0; j < 4; j++) {
            acc[j].x += ta * xv[j].x; acc[j].y += ta * xv[j].y;
            acc[j].z += ta * xv[j].z; acc[j].w += ta * xv[j].w;
        }
    }
#pragma unroll
    for (int j = 0; j < 4; j++) s4[warp * 128 + 32 * j + lane] = acc[j];
    if (lane == 0) s_T[warp] = tsum;
    __syncthreads();

    const float* s = (const float*)s4;
    float v0 = 0.f, v1 = 0.f;
#pragma unroll
    for (int w = 0; w < NW; w++) {
        v0 += s[w * 512 + tid];
        v1 += s[w * 512 + tid + 256];
    }
    float* dst = g_xtp + ((size_t)c * NB + b) * ND;
    dst[tid] = v0;
    dst[tid + 256] = v1;
    if (tid == 0) {
        float t = 0.f;
#pragma unroll
        for (int w = 0; w < NW; w++) t += s_T[w];
        g_Tp[c * NB + b] = t;
    }
}

// ---------------------------------------------------------------------------
// Reduce xt partials + T partials. grid 32, 512 threads
// ---------------------------------------------------------------------------
__global__ __launch_bounds__(512) void k_red2() {
    const int i = blockIdx.x * 512 + threadIdx.x;
    float v = 0.f;
#pragma unroll
    for (int c = 0; c < C2; c++) v += g_xtp[(size_t)c * NB * ND + i];
    g_xt[i] = v;

    if (blockIdx.x == 0 && threadIdx.x < NB) {
        float t = 0.f;
#pragma unroll
        for (int c = 0; c < C2; c++) t += g_Tp[c * NB + threadIdx.x];
        g_T[threadIdx.x] = t;
    }
}

// ---------------------------------------------------------------------------
// latent[b,f] = Wv[f,:].xt[b,:] + bv[f]*T[b]    (warp per output)
// grid (NB, NF/8), 256 threads
// ---------------------------------------------------------------------------
__global__ __launch_bounds__(256) void k_out(const float* __restrict__ Wv,
                                             const float* __restrict__ bv,
                                             float* __restrict__ out) {
    const int b = blockIdx.x;
    const int warp = threadIdx.x >> 5, lane = threadIdx.x & 31;
    const int f = blockIdx.y * 8 + warp;

    const float4* wv = (const float4*)Wv + (size_t)f * (ND / 4);
    const float4* xt = (const float4*)(g_xt + b * ND);
    float dot = 0.f;
#pragma unroll
    for (int q = 0; q < 4; q++) {
        float4 w = wv[32 * q + lane];
        float4 v = xt[32 * q + lane];
        dot += w.x * v.x + w.y * v.y + w.z * v.z + w.w * v.w;
    }
#pragma unroll
    for (int off = 16; off; off >>= 1) dot += __shfl_xor_sync(0xffffffffu, dot, off);
    if (lane == 0) out[b * NF + f] = dot + bv[f] * g_T[b];
}

// ---------------------------------------------------------------------------
extern "C" void kernel_launch(void* const* d_in, const int* in_sizes, int n_in,
                              void* d_out, int out_size) {
    const float* x  = (const float*)d_in[0];
    const float* Wq = (const float*)d_in[1];
    const float* bq = (const float*)d_in[2];
    const float* Wk = (const float*)d_in[3];
    const float* bk = (const float*)d_in[4];
    const float* Wv = (const float*)d_in[5];
    const float* bv = (const float*)d_in[6];
    const float* Wt = (const float*)d_in[7];
    const float* bt = (const float*)d_in[8];
    float* out = (float*)d_out;

    k_xw   <<<dim3(NB, C1), 256>>>(x, Wt);
    k_red1 <<<32, 512>>>(Wt);
    k_kw   <<<dim3(NB, NF / 8), 256>>>(Wk, bk);
    k_u    <<<dim3(NB, 8), 512>>>(Wq, bq);
    k_pass2<<<dim3(NB, C2), 256>>>(x, bt);
    k_red2 <<<32, 512>>>();
    k_out  <<<dim3(NB, NF / 8), 256>>>(Wv, bv, out);
}